// round 15
// baseline (speedup 1.0000x reference)
#include <cuda_runtime.h>
#include <cstdint>

// RandomizedOscillatorsNetwork: B=128, T=1024, I=64, H=512, dt=0.042
// R14 = R1 base (best measured: 3894us; CC=64, Tc=2, KSLICES=16, 1 CTA/SM)
// with ONE change: warp-decentralized barrier.
//   per warp: stcg -> syncwarp -> lane0 red.release(+1); target 128*(t+1)
//   out-STG + x staging between release and poll
//   per-warp poll (lane0+syncwarp) -> per-warp refill of its 1KB a_s slice
//   4 bar.sync/step -> 2 bar.sync/step
// R10's 2-CTA/SM variant reverted (grid imbalance + doubled broadcast LDS).

#define DT_F      0.042f
#define B_        128
#define T_        1024
#define I_        64
#define H_        512
#define KAUG      576           // H_ + I_
#define NCOL      8
#define NGRP      16
#define BC        8             // batches per CTA
#define CC        64            // columns per CTA
#define WPITCH    580           // 4*odd -> conflict-free float4 LDS
#define NTHREADS  512
#define NWARPS    16
#define KSLICES   16
#define KCHUNK4   9             // float4 per k-slice (36 floats)
#define AROW4     (KAUG / 4)    // 144
#define WROW4     (WPITCH / 4)  // 145

__device__ unsigned g_bar[NGRP];
__device__ float    g_hy_ex[2][NGRP][BC][H_];

__device__ __forceinline__ unsigned ld_acquire_u32(const unsigned* p) {
    unsigned v;
    asm volatile("ld.acquire.gpu.u32 %0, [%1];" : "=r"(v) : "l"(p) : "memory");
    return v;
}
__device__ __forceinline__ void red_release_add(unsigned* p, unsigned v) {
    asm volatile("red.release.gpu.global.add.u32 [%0], %1;" :: "l"(p), "r"(v) : "memory");
}

__global__ void ron_init_kernel() {
    if (threadIdx.x < NGRP) g_bar[threadIdx.x] = 0u;
}

__global__ void __launch_bounds__(NTHREADS, 1)
ron_scan_kernel(const float* __restrict__ x,      // [B, T, I]
                const float* __restrict__ x2h,    // [I, H]
                const float* __restrict__ h2h,    // [H, H]
                const float* __restrict__ bias,   // [H]
                const float* __restrict__ gamma_, // [H]
                const float* __restrict__ eps_,   // [H]
                float* __restrict__ out,          // [B*T*H] (+ optional [B*H] tail)
                int write_tail)
{
    extern __shared__ float smem[];
    float* W_s     = smem;                        // [CC][WPITCH] augmented weights, c-major
    float* a_s     = W_s + CC * WPITCH;           // [BC][KAUG]   hy | x_t
    float* partial = a_s + BC * KAUG;             // [KSLICES][BC][CC]

    const int tid  = threadIdx.x;
    const int wid  = tid >> 5;
    const int lane = tid & 31;
    const int g    = blockIdx.x >> 3;
    const int j    = blockIdx.x & 7;
    const int b0   = g * BC;
    const int cg0  = j * CC;

    // matvec role
    const int ks  = tid >> 5;            // 0..15 k-slice
    const int c0  = tid & 31;            // local column (pair: c0, c0+32)
    // elementwise role
    const int eb  = tid >> 6;            // 0..7 local batch
    const int ec  = tid & 63;            // 0..63 local column

    // ---- Prologue ----
    for (int idx = tid; idx < KAUG * CC; idx += NTHREADS) {
        int k  = idx >> 6;
        int cc = idx & 63;
        float w = (k < H_) ? h2h[(size_t)k * H_ + cg0 + cc]
                           : x2h[(size_t)(k - H_) * H_ + cg0 + cc];
        W_s[cc * WPITCH + k] = w;
    }
    for (int idx = tid; idx < BC * H_; idx += NTHREADS) {
        int b = idx >> 9, k = idx & 511;
        a_s[b * KAUG + k] = 0.0f;
    }
    a_s[eb * KAUG + H_ + ec] = x[((size_t)(b0 + eb) * T_ + 0) * I_ + ec];

    const float bia = bias  [cg0 + ec];
    const float gam = gamma_[cg0 + ec];
    const float ep  = eps_  [cg0 + ec];

    __syncthreads();

    float hy_reg = 0.0f, hz = 0.0f;

    const float4* W4  = reinterpret_cast<const float4*>(W_s);
    const float4* A4  = reinterpret_cast<const float4*>(a_s);
    float4*       A4w = reinterpret_cast<float4*>(a_s);
    const size_t w0base = (size_t)c0 * WROW4 + (size_t)ks * KCHUNK4;
    const size_t w1base = w0base + (size_t)32 * WROW4;

    for (int t = 0; t < T_; t++) {
        // prefetch next-step input (LDG latency hidden under matvec)
        float xnext = 0.0f;
        if (t + 1 < T_)
            xnext = x[((size_t)(b0 + eb) * T_ + (t + 1)) * I_ + ec];

        // ---- Matvec: Tc=2 columns x Tb=8 batches per thread over its k-chunk ----
        float acc0[BC], acc1[BC];
        #pragma unroll
        for (int b = 0; b < BC; b++) { acc0[b] = 0.0f; acc1[b] = 0.0f; }

        #pragma unroll
        for (int kb = 0; kb < KCHUNK4; kb++) {
            float4 w0 = W4[w0base + kb];
            float4 w1 = W4[w1base + kb];
            #pragma unroll
            for (int b = 0; b < BC; b++) {
                float4 av = A4[b * AROW4 + ks * KCHUNK4 + kb];
                acc0[b] = fmaf(av.x, w0.x, acc0[b]);
                acc0[b] = fmaf(av.y, w0.y, acc0[b]);
                acc0[b] = fmaf(av.z, w0.z, acc0[b]);
                acc0[b] = fmaf(av.w, w0.w, acc0[b]);
                acc1[b] = fmaf(av.x, w1.x, acc1[b]);
                acc1[b] = fmaf(av.y, w1.y, acc1[b]);
                acc1[b] = fmaf(av.z, w1.z, acc1[b]);
                acc1[b] = fmaf(av.w, w1.w, acc1[b]);
            }
        }

        // ---- k-split partial stores ----
        #pragma unroll
        for (int b = 0; b < BC; b++) {
            partial[ks * (BC * CC) + b * CC + c0]      = acc0[b];
            partial[ks * (BC * CC) + b * CC + c0 + 32] = acc1[b];
        }
        __syncthreads();   // #1: partials ready; matvec reads of a_s done

        // ---- reduce + oscillator update ----
        float v = 0.0f;
        #pragma unroll
        for (int s = 0; s < KSLICES; s++)
            v += partial[s * (BC * CC) + eb * CC + ec];

        float act = tanhf(v + bia);
        hz     = hz + DT_F * (act - gam * hy_reg - ep * hz);
        hy_reg = hy_reg + DT_F * hz;

        if (t + 1 == T_) {
            out[((size_t)(b0 + eb) * T_ + t) * H_ + cg0 + ec] = hy_reg;
            if (write_tail)
                out[(size_t)B_ * T_ * H_ + (size_t)(b0 + eb) * H_ + cg0 + ec] = hy_reg;
            break;
        }

        // ---- warp-decentralized publish + release ----
        __stcg(&g_hy_ex[t & 1][g][eb][cg0 + ec], hy_reg);
        __syncwarp();                       // order this warp's stcg
        if (lane == 0)
            red_release_add(&g_bar[g], 1u); // one release per warp

        // off-critical-path work fills the wait gap
        out[((size_t)(b0 + eb) * T_ + t) * H_ + cg0 + ec] = hy_reg;
        a_s[eb * KAUG + H_ + ec] = xnext;   // safe: all matvec reads done (bar#1)

        // ---- per-warp acquire-poll, then per-warp refill of its a_s slice ----
        {
            const unsigned target = (unsigned)(NWARPS * NCOL * (t + 1)); // 128*(t+1)
            if (lane == 0)
                while (ld_acquire_u32(&g_bar[g]) < target) { }
            __syncwarp();

            const float4* G4 = reinterpret_cast<const float4*>(&g_hy_ex[t & 1][g][0][0]);
            #pragma unroll
            for (int i = 0; i < 2; i++) {
                int idx = wid * 64 + lane + i * 32;    // float4 index 0..1023
                int b   = idx >> 7;                    // 128 float4 per 512-float row
                int k4  = idx & 127;
                A4w[b * AROW4 + k4] = __ldcg(&G4[idx]);
            }
        }
        __syncthreads();   // #2: a_s fully refilled for next matvec
    }
}

extern "C" void kernel_launch(void* const* d_in, const int* in_sizes, int n_in,
                              void* d_out, int out_size)
{
    const float* x      = (const float*)d_in[0];
    const float* x2h    = (const float*)d_in[1];
    const float* h2h    = (const float*)d_in[2];
    const float* bias   = (const float*)d_in[3];
    const float* gamma_ = (const float*)d_in[4];
    const float* eps_   = (const float*)d_in[5];
    float* out = (float*)d_out;

    const int smem_bytes = (CC * WPITCH + BC * KAUG + KSLICES * BC * CC) * 4; // 199,680
    cudaFuncSetAttribute(ron_scan_kernel,
                         cudaFuncAttributeMaxDynamicSharedMemorySize, smem_bytes);

    const int write_tail = (out_size > B_ * T_ * H_) ? 1 : 0;

    ron_init_kernel<<<1, 32>>>();
    ron_scan_kernel<<<NGRP * NCOL, NTHREADS, smem_bytes>>>(
        x, x2h, h2h, bias, gamma_, eps_, out, write_tail);
}